// round 1
// baseline (speedup 1.0000x reference)
#include <cuda_runtime.h>

#define NN 50000
#define NE 800000
#define DIM 128
#define NHEADS 8
#define NEG_SLOPE 0.2f

// ---- scratch (static device globals; no allocation allowed) ----
__device__ float g_xl[NN * DIM];          // x @ Wl + bl
__device__ float g_xr[NN * DIM];          // x @ Wr + br
__device__ float g_attr_sum[NN * 8];      // per-dst sum of one-hot edge_attr
__device__ float g_denom[NN * NHEADS];    // per-dst per-head sum of exp(score)

// ---------------------------------------------------------------------------
// Zero the accumulators (d_out is used as the numerator accumulator).
// ---------------------------------------------------------------------------
__global__ void zero_kernel(float4* __restrict__ out) {
    int idx = blockIdx.x * blockDim.x + threadIdx.x;
    int stride = gridDim.x * blockDim.x;
    float4 z = make_float4(0.f, 0.f, 0.f, 0.f);
    for (int i = idx; i < NN * DIM / 4; i += stride) out[i] = z;
    float4* dn = reinterpret_cast<float4*>(g_denom);
    float4* as = reinterpret_cast<float4*>(g_attr_sum);
    for (int i = idx; i < NN * 8 / 4; i += stride) { dn[i] = z; as[i] = z; }
}

// ---------------------------------------------------------------------------
// GEMM: out = x @ W + b for both (Wl,bl)->g_xl and (Wr,br)->g_xr.
// BM=64, BN=128 (full), BK=32. 256 threads, 8x4 per-thread tile.
// ---------------------------------------------------------------------------
__global__ void gemm_kernel(const float* __restrict__ x,
                            const float* __restrict__ Wl, const float* __restrict__ bl,
                            const float* __restrict__ Wr, const float* __restrict__ br) {
    const float* W    = blockIdx.y ? Wr : Wl;
    const float* bias = blockIdx.y ? br : bl;
    float* out        = blockIdx.y ? g_xr : g_xl;

    __shared__ float xs[64][32];
    __shared__ float ws[32][128];

    int row0 = blockIdx.x * 64;
    int tid = threadIdx.x;
    int tx = tid & 31;   // 32 column groups * 4 cols = 128
    int ty = tid >> 5;   // 8 row groups * 8 rows = 64

    float acc[8][4];
#pragma unroll
    for (int i = 0; i < 8; i++)
#pragma unroll
        for (int j = 0; j < 4; j++) acc[i][j] = 0.f;

    for (int k0 = 0; k0 < DIM; k0 += 32) {
        // load x tile: 64x32 = 512 float4
        int i = tid;
#pragma unroll
        for (int rep = 0; rep < 2; rep++, i += 256) {
            int r = i >> 3, kq = i & 7;
            int grow = row0 + r;
            float4 v = make_float4(0.f, 0.f, 0.f, 0.f);
            if (grow < NN)
                v = *reinterpret_cast<const float4*>(&x[grow * DIM + k0 + kq * 4]);
            *reinterpret_cast<float4*>(&xs[r][kq * 4]) = v;
        }
        // load W tile: 32x128 = 1024 float4
        i = tid;
#pragma unroll
        for (int rep = 0; rep < 4; rep++, i += 256) {
            int kr = i >> 5, cq = i & 31;
            *reinterpret_cast<float4*>(&ws[kr][cq * 4]) =
                *reinterpret_cast<const float4*>(&W[(k0 + kr) * DIM + cq * 4]);
        }
        __syncthreads();

#pragma unroll
        for (int kk = 0; kk < 32; kk++) {
            float4 b4 = *reinterpret_cast<float4*>(&ws[kk][tx * 4]);
#pragma unroll
            for (int r = 0; r < 8; r++) {
                float a = xs[ty * 8 + r][kk];  // broadcast within warp
                acc[r][0] += a * b4.x;
                acc[r][1] += a * b4.y;
                acc[r][2] += a * b4.z;
                acc[r][3] += a * b4.w;
            }
        }
        __syncthreads();
    }

    float4 bb = *reinterpret_cast<const float4*>(&bias[tx * 4]);
#pragma unroll
    for (int r = 0; r < 8; r++) {
        int row = row0 + ty * 8 + r;
        if (row < NN) {
            float4 v = make_float4(acc[r][0] + bb.x, acc[r][1] + bb.y,
                                   acc[r][2] + bb.z, acc[r][3] + bb.w);
            *reinterpret_cast<float4*>(&out[row * DIM + tx * 4]) = v;
        }
    }
}

// ---------------------------------------------------------------------------
// Edge pass: one warp per edge.
//   score_h = att_h . leaky_relu(xl[src] + xr[dst] + We[etype])
//   w = exp(score_h)  (no max-subtraction: scores are O(7), exp() safe in fp32,
//                      ratios identical to the max-stabilized form)
//   num[dst] += w * xl[src]      (red.global.add.v4.f32)
//   denom[dst,h] += w
//   attr_sum[dst,t] += 1
// ---------------------------------------------------------------------------
__global__ void edge_kernel(const int* __restrict__ src, const int* __restrict__ dst,
                            const float* __restrict__ edge_attr,
                            const float* __restrict__ We, const float* __restrict__ att,
                            float* __restrict__ num) {
    __shared__ float sWe[8 * DIM];
    for (int i = threadIdx.x; i < 8 * DIM; i += blockDim.x) sWe[i] = We[i];
    __syncthreads();

    int lane = threadIdx.x & 31;
    int warp = threadIdx.x >> 5;
    int e = blockIdx.x * (blockDim.x >> 5) + warp;
    if (e >= NE) return;

    // lane covers channels [4*lane, 4*lane+3]; head h = lane>>2.
    float4 attv = reinterpret_cast<const float4*>(att)[lane];

    int s = src[e], d = dst[e];
    float av = (lane < 8) ? edge_attr[e * 8 + lane] : 0.f;
    unsigned m = __ballot_sync(0xffffffffu, av > 0.5f);
    int t = __ffs(m) - 1;  // one-hot index

    float4 vl = reinterpret_cast<const float4*>(g_xl)[s * 32 + lane];
    float4 vr = reinterpret_cast<const float4*>(g_xr)[d * 32 + lane];
    float4 ve = reinterpret_cast<const float4*>(sWe)[t * 32 + lane];

    float ex = vl.x + vr.x + ve.x; ex = ex > 0.f ? ex : NEG_SLOPE * ex;
    float ey = vl.y + vr.y + ve.y; ey = ey > 0.f ? ey : NEG_SLOPE * ey;
    float ez = vl.z + vr.z + ve.z; ez = ez > 0.f ? ez : NEG_SLOPE * ez;
    float ew = vl.w + vr.w + ve.w; ew = ew > 0.f ? ew : NEG_SLOPE * ew;

    float p = ex * attv.x + ey * attv.y + ez * attv.z + ew * attv.w;
    p += __shfl_xor_sync(0xffffffffu, p, 1);
    p += __shfl_xor_sync(0xffffffffu, p, 2);  // all 4 lanes of head group hold score_h

    float w = __expf(p);

    float* dp = &num[d * DIM + lane * 4];
    asm volatile("red.global.add.v4.f32 [%0], {%1,%2,%3,%4};"
                 :: "l"(dp), "f"(vl.x * w), "f"(vl.y * w), "f"(vl.z * w), "f"(vl.w * w)
                 : "memory");
    if ((lane & 3) == 0) atomicAdd(&g_denom[d * NHEADS + (lane >> 2)], w);
    if (lane == 0) atomicAdd(&g_attr_sum[d * 8 + t], 1.0f);
}

// ---------------------------------------------------------------------------
// Node epilogue: one warp per node. Adds the self-loop term, normalizes,
// adds bias, LayerNorm, ELU. Reads num from d_out, writes final result back.
// ---------------------------------------------------------------------------
__global__ void node_kernel(const float* __restrict__ We, const float* __restrict__ att,
                            const float* __restrict__ bias, const float* __restrict__ ln_w,
                            const float* __restrict__ ln_b, float* __restrict__ out) {
    __shared__ float sWe[8 * DIM];
    for (int i = threadIdx.x; i < 8 * DIM; i += blockDim.x) sWe[i] = We[i];
    __syncthreads();

    int lane = threadIdx.x & 31;
    int warp = threadIdx.x >> 5;
    int n = blockIdx.x * (blockDim.x >> 5) + warp;
    if (n >= NN) return;

    // self-loop attr = attr_sum / max(deg, 1)
    float as = (lane < 8) ? g_attr_sum[n * 8 + lane] : 0.f;
    float deg = as;
    deg += __shfl_xor_sync(0xffffffffu, deg, 1);
    deg += __shfl_xor_sync(0xffffffffu, deg, 2);
    deg += __shfl_xor_sync(0xffffffffu, deg, 4);
    float la = as / fmaxf(deg, 1.f);

    float4 emb = make_float4(0.f, 0.f, 0.f, 0.f);
#pragma unroll
    for (int t = 0; t < 8; t++) {
        float lt = __shfl_sync(0xffffffffu, la, t);
        float4 wv = reinterpret_cast<float4*>(sWe)[t * 32 + lane];
        emb.x += lt * wv.x; emb.y += lt * wv.y;
        emb.z += lt * wv.z; emb.w += lt * wv.w;
    }

    float4 vl = reinterpret_cast<const float4*>(g_xl)[n * 32 + lane];
    float4 vr = reinterpret_cast<const float4*>(g_xr)[n * 32 + lane];
    float4 attv = reinterpret_cast<const float4*>(att)[lane];

    float ex = vl.x + vr.x + emb.x; ex = ex > 0.f ? ex : NEG_SLOPE * ex;
    float ey = vl.y + vr.y + emb.y; ey = ey > 0.f ? ey : NEG_SLOPE * ey;
    float ez = vl.z + vr.z + emb.z; ez = ez > 0.f ? ez : NEG_SLOPE * ez;
    float ew = vl.w + vr.w + emb.w; ew = ew > 0.f ? ew : NEG_SLOPE * ew;

    float p = ex * attv.x + ey * attv.y + ez * attv.z + ew * attv.w;
    p += __shfl_xor_sync(0xffffffffu, p, 1);
    p += __shfl_xor_sync(0xffffffffu, p, 2);
    float w = __expf(p);

    int h = lane >> 2;
    float den = g_denom[n * NHEADS + h] + w;

    float4 num = reinterpret_cast<float4*>(out)[n * 32 + lane];
    float4 bb = reinterpret_cast<const float4*>(bias)[lane];
    float inv_den = 1.f / den;
    float4 o;
    o.x = (num.x + w * vl.x) * inv_den + bb.x;
    o.y = (num.y + w * vl.y) * inv_den + bb.y;
    o.z = (num.z + w * vl.z) * inv_den + bb.z;
    o.w = (num.w + w * vl.w) * inv_den + bb.w;

    // LayerNorm over 128 channels (two-pass, matches reference)
    float ssum = o.x + o.y + o.z + o.w;
#pragma unroll
    for (int m = 1; m < 32; m <<= 1) ssum += __shfl_xor_sync(0xffffffffu, ssum, m);
    float mu = ssum * (1.f / 128.f);

    float dx = o.x - mu, dy = o.y - mu, dz = o.z - mu, dw = o.w - mu;
    float sq = dx * dx + dy * dy + dz * dz + dw * dw;
#pragma unroll
    for (int m = 1; m < 32; m <<= 1) sq += __shfl_xor_sync(0xffffffffu, sq, m);
    float inv = rsqrtf(sq * (1.f / 128.f) + 1e-5f);

    float4 lw = reinterpret_cast<const float4*>(ln_w)[lane];
    float4 lb = reinterpret_cast<const float4*>(ln_b)[lane];
    o.x = dx * inv * lw.x + lb.x;
    o.y = dy * inv * lw.y + lb.y;
    o.z = dz * inv * lw.z + lb.z;
    o.w = dw * inv * lw.w + lb.w;

    // ELU
    o.x = o.x > 0.f ? o.x : expm1f(o.x);
    o.y = o.y > 0.f ? o.y : expm1f(o.y);
    o.z = o.z > 0.f ? o.z : expm1f(o.z);
    o.w = o.w > 0.f ? o.w : expm1f(o.w);

    reinterpret_cast<float4*>(out)[n * 32 + lane] = o;
}

// ---------------------------------------------------------------------------
extern "C" void kernel_launch(void* const* d_in, const int* in_sizes, int n_in,
                              void* d_out, int out_size) {
    const float* x         = (const float*)d_in[0];
    const int*   src       = (const int*)  d_in[1];
    const int*   dst       = (const int*)  d_in[2];
    const float* edge_attr = (const float*)d_in[3];
    const float* Wl        = (const float*)d_in[4];
    const float* bl        = (const float*)d_in[5];
    const float* Wr        = (const float*)d_in[6];
    const float* br        = (const float*)d_in[7];
    const float* We        = (const float*)d_in[8];
    const float* att       = (const float*)d_in[9];
    const float* bias      = (const float*)d_in[10];
    const float* ln_w      = (const float*)d_in[11];
    const float* ln_b      = (const float*)d_in[12];
    float* out = (float*)d_out;

    zero_kernel<<<2048, 256>>>((float4*)out);
    gemm_kernel<<<dim3((NN + 63) / 64, 2), 256>>>(x, Wl, bl, Wr, br);
    edge_kernel<<<NE / 8, 256>>>(src, dst, edge_attr, We, att, out);
    node_kernel<<<(NN + 7) / 8, 256>>>(We, att, bias, ln_w, ln_b, out);
}

// round 2
// speedup vs baseline: 1.1437x; 1.1437x over previous
#include <cuda_runtime.h>

#define NN 50000
#define NE 800000
#define DIM 128
#define NHEADS 8
#define NEG_SLOPE 0.2f

// ---- scratch (static device globals; no allocation allowed) ----
__device__ float g_xl[NN * DIM];           // x @ Wl + bl
__device__ float g_xr[NN * DIM];           // x @ Wr + br
__device__ int   g_cnt[NN];                // in-degree
__device__ int   g_row[NN + 1];            // CSR row starts (exclusive scan)
__device__ int   g_cur[NN];                // scatter cursors
__device__ unsigned g_entry[NE];           // packed (src | type<<16) per edge, grouped by dst

// ---------------------------------------------------------------------------
__global__ void zero_cnt_kernel() {
    int i = blockIdx.x * blockDim.x + threadIdx.x;
    if (i < NN) g_cnt[i] = 0;
}

__global__ void count_kernel(const int* __restrict__ dst) {
    int e = blockIdx.x * blockDim.x + threadIdx.x;
    if (e < NE) atomicAdd(&g_cnt[dst[e]], 1);
}

// Single-block exclusive scan over g_cnt -> g_row, g_cur. 1024 threads.
__global__ void scan_kernel() {
    __shared__ int s_warp[32];
    __shared__ int s_carry;
    int tid = threadIdx.x;
    int lane = tid & 31, wid = tid >> 5;
    if (tid == 0) s_carry = 0;
    __syncthreads();

    for (int base = 0; base < NN; base += 1024) {
        int i = base + tid;
        int c = (i < NN) ? g_cnt[i] : 0;
        int v = c;
#pragma unroll
        for (int d = 1; d < 32; d <<= 1) {
            int t = __shfl_up_sync(0xffffffffu, v, d);
            if (lane >= d) v += t;
        }
        if (lane == 31) s_warp[wid] = v;
        __syncthreads();
        if (wid == 0) {
            int wv = s_warp[lane];
#pragma unroll
            for (int d = 1; d < 32; d <<= 1) {
                int t = __shfl_up_sync(0xffffffffu, wv, d);
                if (lane >= d) wv += t;
            }
            s_warp[lane] = wv;
        }
        __syncthreads();
        int carry_old = s_carry;
        int excl = carry_old + (wid > 0 ? s_warp[wid - 1] : 0) + v - c;
        if (i < NN) { g_row[i] = excl; g_cur[i] = excl; }
        __syncthreads();
        if (tid == 0) s_carry = carry_old + s_warp[31];
        __syncthreads();
    }
    if (tid == 0) g_row[NN] = s_carry;
}

__global__ void scatter_kernel(const int* __restrict__ src, const int* __restrict__ dst,
                               const float* __restrict__ edge_attr) {
    int e = blockIdx.x * blockDim.x + threadIdx.x;
    if (e >= NE) return;
    int t = 0;
#pragma unroll
    for (int k = 1; k < 8; k++)
        if (edge_attr[e * 8 + k] > 0.5f) t = k;
    int pos = atomicAdd(&g_cur[dst[e]], 1);
    g_entry[pos] = (unsigned)src[e] | ((unsigned)t << 16);
}

// ---------------------------------------------------------------------------
// GEMM: out = x @ W + b for both (Wl,bl)->g_xl and (Wr,br)->g_xr.
// BM=64, BN=128 (full), BK=32. 256 threads, 8x4 per-thread tile.
// ---------------------------------------------------------------------------
__global__ void gemm_kernel(const float* __restrict__ x,
                            const float* __restrict__ Wl, const float* __restrict__ bl,
                            const float* __restrict__ Wr, const float* __restrict__ br) {
    const float* W    = blockIdx.y ? Wr : Wl;
    const float* bias = blockIdx.y ? br : bl;
    float* out        = blockIdx.y ? g_xr : g_xl;

    __shared__ float xs[64][32];
    __shared__ float ws[32][128];

    int row0 = blockIdx.x * 64;
    int tid = threadIdx.x;
    int tx = tid & 31;
    int ty = tid >> 5;

    float acc[8][4];
#pragma unroll
    for (int i = 0; i < 8; i++)
#pragma unroll
        for (int j = 0; j < 4; j++) acc[i][j] = 0.f;

    for (int k0 = 0; k0 < DIM; k0 += 32) {
        int i = tid;
#pragma unroll
        for (int rep = 0; rep < 2; rep++, i += 256) {
            int r = i >> 3, kq = i & 7;
            int grow = row0 + r;
            float4 v = make_float4(0.f, 0.f, 0.f, 0.f);
            if (grow < NN)
                v = *reinterpret_cast<const float4*>(&x[grow * DIM + k0 + kq * 4]);
            *reinterpret_cast<float4*>(&xs[r][kq * 4]) = v;
        }
        i = tid;
#pragma unroll
        for (int rep = 0; rep < 4; rep++, i += 256) {
            int kr = i >> 5, cq = i & 31;
            *reinterpret_cast<float4*>(&ws[kr][cq * 4]) =
                *reinterpret_cast<const float4*>(&W[(k0 + kr) * DIM + cq * 4]);
        }
        __syncthreads();

#pragma unroll
        for (int kk = 0; kk < 32; kk++) {
            float4 b4 = *reinterpret_cast<float4*>(&ws[kk][tx * 4]);
#pragma unroll
            for (int r = 0; r < 8; r++) {
                float a = xs[ty * 8 + r][kk];
                acc[r][0] += a * b4.x;
                acc[r][1] += a * b4.y;
                acc[r][2] += a * b4.z;
                acc[r][3] += a * b4.w;
            }
        }
        __syncthreads();
    }

    float4 bb = *reinterpret_cast<const float4*>(&bias[tx * 4]);
#pragma unroll
    for (int r = 0; r < 8; r++) {
        int row = row0 + ty * 8 + r;
        if (row < NN) {
            float4 v = make_float4(acc[r][0] + bb.x, acc[r][1] + bb.y,
                                   acc[r][2] + bb.z, acc[r][3] + bb.w);
            *reinterpret_cast<float4*>(&out[row * DIM + tx * 4]) = v;
        }
    }
}

// ---------------------------------------------------------------------------
// Gather + full epilogue: one warp per destination node.
// Register-accumulated softmax aggregation (no atomics), then self-loop,
// normalize, bias, LayerNorm, ELU, write final output.
// ---------------------------------------------------------------------------
__global__ void gather_kernel(const float* __restrict__ We, const float* __restrict__ att,
                              const float* __restrict__ bias, const float* __restrict__ ln_w,
                              const float* __restrict__ ln_b, float* __restrict__ out) {
    __shared__ float sWe[8 * DIM];
    for (int i = threadIdx.x; i < 8 * DIM; i += blockDim.x) sWe[i] = We[i];
    __syncthreads();

    int lane = threadIdx.x & 31;
    int warp = threadIdx.x >> 5;
    int n = blockIdx.x * (blockDim.x >> 5) + warp;
    if (n >= NN) return;

    const float4* xl4 = reinterpret_cast<const float4*>(g_xl);
    const float4* sWe4 = reinterpret_cast<const float4*>(sWe);
    float4 attv = reinterpret_cast<const float4*>(att)[lane];

    int start = g_row[n];
    int end   = g_row[n + 1];

    float4 xr4 = reinterpret_cast<const float4*>(g_xr)[n * 32 + lane];
    float4 xls = xl4[n * 32 + lane];  // self-loop source features

    float4 acc = make_float4(0.f, 0.f, 0.f, 0.f);
    float den = 0.f;
    float tcnt = 0.f;  // lane<8: count of incoming edges of type==lane

    for (int base = start; base < end; base += 32) {
        int m = min(32, end - base);
        unsigned ent = (lane < m) ? g_entry[base + lane] : 0u;

        // 2-stage software pipeline over the m edges
        unsigned e0 = __shfl_sync(0xffffffffu, ent, 0);
        int s0 = e0 & 0xFFFF, t0 = e0 >> 16;
        float4 v0 = __ldg(&xl4[s0 * 32 + lane]);

        for (int j = 0; j < m; j++) {
            int s1 = 0, t1 = 0;
            float4 v1 = v0;
            if (j + 1 < m) {
                unsigned e1 = __shfl_sync(0xffffffffu, ent, j + 1);
                s1 = e1 & 0xFFFF; t1 = e1 >> 16;
                v1 = __ldg(&xl4[s1 * 32 + lane]);
            }
            float4 wv = sWe4[t0 * 32 + lane];
            float ex = v0.x + xr4.x + wv.x; ex = ex > 0.f ? ex : NEG_SLOPE * ex;
            float ey = v0.y + xr4.y + wv.y; ey = ey > 0.f ? ey : NEG_SLOPE * ey;
            float ez = v0.z + xr4.z + wv.z; ez = ez > 0.f ? ez : NEG_SLOPE * ez;
            float ew = v0.w + xr4.w + wv.w; ew = ew > 0.f ? ew : NEG_SLOPE * ew;
            float p = ex * attv.x + ey * attv.y + ez * attv.z + ew * attv.w;
            p += __shfl_xor_sync(0xffffffffu, p, 1);
            p += __shfl_xor_sync(0xffffffffu, p, 2);
            float w = __expf(p);
            acc.x += w * v0.x; acc.y += w * v0.y;
            acc.z += w * v0.z; acc.w += w * v0.w;
            den += w;
            tcnt += (lane == t0) ? 1.f : 0.f;
            s0 = s1; t0 = t1; v0 = v1;
        }
    }

    // self-loop: attr = per-type count / max(deg,1), emb = attr @ We
    int deg = end - start;
    float maxdeg = fmaxf((float)deg, 1.f);
    float4 emb = make_float4(0.f, 0.f, 0.f, 0.f);
#pragma unroll
    for (int t = 0; t < 8; t++) {
        float lt = __shfl_sync(0xffffffffu, tcnt, t) / maxdeg;
        float4 wv = sWe4[t * 32 + lane];
        emb.x += lt * wv.x; emb.y += lt * wv.y;
        emb.z += lt * wv.z; emb.w += lt * wv.w;
    }
    {
        float ex = xls.x + xr4.x + emb.x; ex = ex > 0.f ? ex : NEG_SLOPE * ex;
        float ey = xls.y + xr4.y + emb.y; ey = ey > 0.f ? ey : NEG_SLOPE * ey;
        float ez = xls.z + xr4.z + emb.z; ez = ez > 0.f ? ez : NEG_SLOPE * ez;
        float ew = xls.w + xr4.w + emb.w; ew = ew > 0.f ? ew : NEG_SLOPE * ew;
        float p = ex * attv.x + ey * attv.y + ez * attv.z + ew * attv.w;
        p += __shfl_xor_sync(0xffffffffu, p, 1);
        p += __shfl_xor_sync(0xffffffffu, p, 2);
        float w = __expf(p);
        acc.x += w * xls.x; acc.y += w * xls.y;
        acc.z += w * xls.z; acc.w += w * xls.w;
        den += w;
    }

    float inv_den = 1.f / den;  // per-lane den matches its head
    float4 bb = reinterpret_cast<const float4*>(bias)[lane];
    float4 o;
    o.x = acc.x * inv_den + bb.x;
    o.y = acc.y * inv_den + bb.y;
    o.z = acc.z * inv_den + bb.z;
    o.w = acc.w * inv_den + bb.w;

    // LayerNorm over 128 channels
    float ssum = o.x + o.y + o.z + o.w;
#pragma unroll
    for (int m = 1; m < 32; m <<= 1) ssum += __shfl_xor_sync(0xffffffffu, ssum, m);
    float mu = ssum * (1.f / 128.f);

    float dx = o.x - mu, dy = o.y - mu, dz = o.z - mu, dw = o.w - mu;
    float sq = dx * dx + dy * dy + dz * dz + dw * dw;
#pragma unroll
    for (int m = 1; m < 32; m <<= 1) sq += __shfl_xor_sync(0xffffffffu, sq, m);
    float inv = rsqrtf(sq * (1.f / 128.f) + 1e-5f);

    float4 lw = reinterpret_cast<const float4*>(ln_w)[lane];
    float4 lb = reinterpret_cast<const float4*>(ln_b)[lane];
    o.x = dx * inv * lw.x + lb.x;
    o.y = dy * inv * lw.y + lb.y;
    o.z = dz * inv * lw.z + lb.z;
    o.w = dw * inv * lw.w + lb.w;

    o.x = o.x > 0.f ? o.x : expm1f(o.x);
    o.y = o.y > 0.f ? o.y : expm1f(o.y);
    o.z = o.z > 0.f ? o.z : expm1f(o.z);
    o.w = o.w > 0.f ? o.w : expm1f(o.w);

    reinterpret_cast<float4*>(out)[n * 32 + lane] = o;
}

// ---------------------------------------------------------------------------
extern "C" void kernel_launch(void* const* d_in, const int* in_sizes, int n_in,
                              void* d_out, int out_size) {
    const float* x         = (const float*)d_in[0];
    const int*   src       = (const int*)  d_in[1];
    const int*   dst       = (const int*)  d_in[2];
    const float* edge_attr = (const float*)d_in[3];
    const float* Wl        = (const float*)d_in[4];
    const float* bl        = (const float*)d_in[5];
    const float* Wr        = (const float*)d_in[6];
    const float* br        = (const float*)d_in[7];
    const float* We        = (const float*)d_in[8];
    const float* att       = (const float*)d_in[9];
    const float* bias      = (const float*)d_in[10];
    const float* ln_w      = (const float*)d_in[11];
    const float* ln_b      = (const float*)d_in[12];
    float* out = (float*)d_out;

    zero_cnt_kernel<<<(NN + 255) / 256, 256>>>();
    count_kernel<<<(NE + 255) / 256, 256>>>(dst);
    scan_kernel<<<1, 1024>>>();
    scatter_kernel<<<(NE + 255) / 256, 256>>>(src, dst, edge_attr);
    gemm_kernel<<<dim3((NN + 63) / 64, 2), 256>>>(x, Wl, bl, Wr, br);
    gather_kernel<<<(NN + 7) / 8, 256>>>(We, att, bias, ln_w, ln_b, out);
}